// round 7
// baseline (speedup 1.0000x reference)
#include <cuda_runtime.h>
#include <cuda_fp16.h>
#include <cstdint>
#include <cstddef>

// Problem shape (fixed by the dataset)
#define MDIM 8192
#define NDIM 4096
#define KDIM 4096

// GEMM tiling
#define TM 128
#define TN 128
#define TKE 32                    // K elements per stage
#define THREADS 256
#define KITERS (KDIM / TKE)       // 128
#define STAGES 4

#define ROWB 80                   // SMEM bytes per tile row (64B data + 16B pad)
#define TILE_BYTES (128 * ROWB)   // 10240
#define STAGE_BYTES (2 * TILE_BYTES)
#define SMEM_DYN (STAGES * STAGE_BYTES)   // 81920

// Staging buffers (scratch: __device__ globals, no allocation)
__device__ __align__(256) __half g_A_f16[(size_t)MDIM * KDIM];  // 64 MB
__device__ __align__(256) __half g_W_f16[(size_t)NDIM * KDIM];  // 32 MB

// ---------------- helpers ----------------
__device__ __forceinline__ uint32_t smem_u32(const void* p) {
    uint32_t a;
    asm("{ .reg .u64 t; cvta.to.shared.u64 t, %1; cvt.u32.u64 %0, t; }" : "=r"(a) : "l"(p));
    return a;
}

__device__ __forceinline__ void cp_async16(uint32_t s, const void* g) {
    asm volatile("cp.async.cg.shared.global [%0], [%1], 16;" :: "r"(s), "l"(g) : "memory");
}

#define CP_COMMIT() asm volatile("cp.async.commit_group;" ::: "memory")
#define CP_WAIT2()  asm volatile("cp.async.wait_group 2;"  ::: "memory")

__device__ __forceinline__ uint32_t lds32(uint32_t addr) {
    uint32_t v;
    asm volatile("ld.shared.b32 %0, [%1];" : "=r"(v) : "r"(addr));
    return v;
}

__device__ __forceinline__ void mma16816(float* c, const uint32_t* a, const uint32_t* b) {
    asm volatile(
        "mma.sync.aligned.m16n8k16.row.col.f32.f16.f16.f32 "
        "{%0,%1,%2,%3}, {%4,%5,%6,%7}, {%8,%9}, {%0,%1,%2,%3};"
        : "+f"(c[0]), "+f"(c[1]), "+f"(c[2]), "+f"(c[3])
        : "r"(a[0]), "r"(a[1]), "r"(a[2]), "r"(a[3]), "r"(b[0]), "r"(b[1]));
}

// ---------------- Kernel 1: fp32 -> fp16 activation convert ----------------
__global__ void __launch_bounds__(256) cvt_a_kernel(const float* __restrict__ in) {
    size_t i = ((size_t)blockIdx.x * blockDim.x + threadIdx.x) * 8;
    float4 v0 = *reinterpret_cast<const float4*>(in + i);
    float4 v1 = *reinterpret_cast<const float4*>(in + i + 4);
    __half2 h0 = __floats2half2_rn(v0.x, v0.y);
    __half2 h1 = __floats2half2_rn(v0.z, v0.w);
    __half2 h2 = __floats2half2_rn(v1.x, v1.y);
    __half2 h3 = __floats2half2_rn(v1.z, v1.w);
    uint4 o;
    o.x = *reinterpret_cast<uint32_t*>(&h0);
    o.y = *reinterpret_cast<uint32_t*>(&h1);
    o.z = *reinterpret_cast<uint32_t*>(&h2);
    o.w = *reinterpret_cast<uint32_t*>(&h3);
    *reinterpret_cast<uint4*>(g_A_f16 + i) = o;
}

// ---------------- Kernel 2: int32-carrier weight -> fp16 convert ----------------
// d_in[1] carries the int8 weight values as int32 (one weight per int32).
__global__ void __launch_bounds__(256) cvt_w_kernel(const int* __restrict__ w) {
    size_t i = ((size_t)blockIdx.x * blockDim.x + threadIdx.x) * 8;
    int4 v0 = *reinterpret_cast<const int4*>(w + i);
    int4 v1 = *reinterpret_cast<const int4*>(w + i + 4);
    __half2 h0 = __floats2half2_rn((float)v0.x, (float)v0.y);
    __half2 h1 = __floats2half2_rn((float)v0.z, (float)v0.w);
    __half2 h2 = __floats2half2_rn((float)v1.x, (float)v1.y);
    __half2 h3 = __floats2half2_rn((float)v1.z, (float)v1.w);
    uint4 o;
    o.x = *reinterpret_cast<uint32_t*>(&h0);
    o.y = *reinterpret_cast<uint32_t*>(&h1);
    o.z = *reinterpret_cast<uint32_t*>(&h2);
    o.w = *reinterpret_cast<uint32_t*>(&h3);
    *reinterpret_cast<uint4*>(g_W_f16 + i) = o;
}

// ---------------- Kernel 3: HMMA GEMM ----------------
// C[128,128] per CTA, 8 warps in 2(m) x 4(n), warp tile 64x32, mma m16n8k16.
// Fragments loaded with scalar ld.shared.b32 at the PTX-ISA documented
// per-lane coordinates.
__global__ void __launch_bounds__(THREADS)
gemm_kernel(const float* __restrict__ scale,
            const float* __restrict__ bias,
            float* __restrict__ out)
{
    extern __shared__ char smem[];
    const uint32_t sbase = smem_u32(smem);

    const int tid = threadIdx.x;
    const int wid = tid >> 5, lane = tid & 31;
    const int tileN = blockIdx.x;
    const int tileM = blockIdx.y;

    const __half* Ag = g_A_f16 + (size_t)(tileM * TM) * KDIM;
    const __half* Bg = g_W_f16 + (size_t)(tileN * TN) * KDIM;

    // cp.async mapping: thread -> (row = tid/2, 2 x 16B chunks)
    const int ld_row = tid >> 1;
    const int ld_cb  = (tid & 1) * 2;     // 16B-chunk base (0 or 2)
    const __half* agp = Ag + (size_t)ld_row * KDIM + ld_cb * 8;
    const __half* bgp = Bg + (size_t)ld_row * KDIM + ld_cb * 8;
    const uint32_t da_base = ld_row * ROWB + ld_cb * 16;

    // warp tiling
    const int m_warp = (wid >> 2) * 64;
    const int n_warp = (wid & 3) * 32;

    // fragment coordinates (PTX ISA m16n8k16)
    const int g  = lane >> 2;       // group id (row within 8)
    const int t4 = (lane & 3) * 4;  // byte offset of the f16 pair

    float acc[4][4][4];
    #pragma unroll
    for (int mt = 0; mt < 4; ++mt)
        #pragma unroll
        for (int nt = 0; nt < 4; ++nt)
            #pragma unroll
            for (int e = 0; e < 4; ++e) acc[mt][nt][e] = 0.f;

    auto load_stage = [&](int s, int kt) {
        const uint32_t sa = sbase + s * STAGE_BYTES + da_base;
        const uint32_t sb = sa + TILE_BYTES;
        const __half* ga = agp + (size_t)kt * TKE;
        const __half* gb = bgp + (size_t)kt * TKE;
        cp_async16(sa,      ga);
        cp_async16(sa + 16, ga + 8);
        cp_async16(sb,      gb);
        cp_async16(sb + 16, gb + 8);
    };

    load_stage(0, 0); CP_COMMIT();
    load_stage(1, 1); CP_COMMIT();
    load_stage(2, 2); CP_COMMIT();

    for (int kt = 0; kt < KITERS; ++kt) {
        CP_WAIT2();
        __syncthreads();

        if (kt + 3 < KITERS) load_stage((kt + 3) & (STAGES - 1), kt + 3);
        CP_COMMIT();

        const uint32_t sa = sbase + (kt & (STAGES - 1)) * STAGE_BYTES;
        const uint32_t sb = sa + TILE_BYTES;

        #pragma unroll
        for (int ks = 0; ks < 2; ++ks) {
            // ---- A fragments: warp rows m_warp + mt*16 + {g, g+8}, k half ks ----
            uint32_t Af[4][4];
            #pragma unroll
            for (int mt = 0; mt < 4; ++mt) {
                uint32_t base = sa + (uint32_t)(m_warp + mt * 16 + g) * ROWB
                              + (uint32_t)(ks * 32 + t4);
                Af[mt][0] = lds32(base);                 // (g,   k 2t..2t+1)
                Af[mt][1] = lds32(base + 8 * ROWB);      // (g+8, k 2t..2t+1)
                Af[mt][2] = lds32(base + 16);            // (g,   k 2t+8..)
                Af[mt][3] = lds32(base + 8 * ROWB + 16); // (g+8, k 2t+8..)
            }
            // ---- B fragments: n rows n_warp + nt*8 + g ----
            uint32_t Bf[4][2];
            #pragma unroll
            for (int nt = 0; nt < 4; ++nt) {
                uint32_t base = sb + (uint32_t)(n_warp + nt * 8 + g) * ROWB
                              + (uint32_t)(ks * 32 + t4);
                Bf[nt][0] = lds32(base);       // (k 2t..,   n g)
                Bf[nt][1] = lds32(base + 16);  // (k 2t+8.., n g)
            }
            #pragma unroll
            for (int mt = 0; mt < 4; ++mt)
                #pragma unroll
                for (int nt = 0; nt < 4; ++nt)
                    mma16816(acc[mt][nt], Af[mt], Bf[nt]);
        }
    }

    // ---- epilogue: scale + bias, float2 stores ----
    const int gm0 = tileM * TM + m_warp + g;
    const int gn0 = tileN * TN + n_warp + (lane & 3) * 2;

    #pragma unroll
    for (int nt = 0; nt < 4; ++nt) {
        const int n = gn0 + nt * 8;
        const float sx = __ldg(scale + n),     bx = __ldg(bias + n);
        const float sy = __ldg(scale + n + 1), by = __ldg(bias + n + 1);
        #pragma unroll
        for (int mt = 0; mt < 4; ++mt) {
            const size_t row0 = (size_t)(gm0 + mt * 16);
            float2 v0, v1;
            v0.x = acc[mt][nt][0] * sx + bx;
            v0.y = acc[mt][nt][1] * sy + by;
            v1.x = acc[mt][nt][2] * sx + bx;
            v1.y = acc[mt][nt][3] * sy + by;
            *reinterpret_cast<float2*>(out + row0 * NDIM + n)       = v0;
            *reinterpret_cast<float2*>(out + (row0 + 8) * NDIM + n) = v1;
        }
    }
}

// ---------------- Launch ----------------
extern "C" void kernel_launch(void* const* d_in, const int* in_sizes, int n_in,
                              void* d_out, int out_size) {
    const float* inp   = (const float*)d_in[0];   // [4, 2048, 4096] fp32
    const int*   w     = (const int*)d_in[1];     // [4096, 4096] int32 carrier of int8 values
    const float* scale = (const float*)d_in[2];   // [4096]
    const float* bias  = (const float*)d_in[3];   // [1, 4096]
    float*       out   = (float*)d_out;           // [8192, 4096] fp32

    (void)in_sizes; (void)n_in; (void)out_size;

    cvt_a_kernel<<<(unsigned)(((size_t)MDIM * KDIM) / (256 * 8)), 256>>>(inp);
    cvt_w_kernel<<<(unsigned)(((size_t)NDIM * KDIM) / (256 * 8)), 256>>>(w);

    cudaFuncSetAttribute(gemm_kernel,
                         cudaFuncAttributeMaxDynamicSharedMemorySize, SMEM_DYN);
    dim3 grid(NDIM / TN, MDIM / TM);   // (32, 64) = 2048 CTAs
    gemm_kernel<<<grid, THREADS, SMEM_DYN>>>(scale, bias, out);
}